// round 12
// baseline (speedup 1.0000x reference)
#include <cuda_runtime.h>
#include <cuda_fp16.h>
#include <cstdint>
#include <cstddef>

// Problem constants
#define NB   4
#define NTQ  256
#define NTK  256
#define ND   1024
#define NA   512

// Scratch (allocation-free rule: __device__ globals).
__device__ __half2 g_qph[NB * NTQ * (NA / 2)];     // [b*TQ+q][a/2]
__device__ uint4   g_kp4[(NA / 8) * NB * NTK];     // [a/8][b*TK+t] : 4x half2

// ---------------------------------------------------------------------------
// Helpers
// ---------------------------------------------------------------------------
__device__ __forceinline__ uint32_t cvta_shared_u32(const void* p) {
    uint32_t a;
    asm("{ .reg .u64 t; cvta.to.shared.u64 t, %1; cvt.u32.u64 %0, t; }"
        : "=r"(a) : "l"(p));
    return a;
}

__device__ __forceinline__ void ldsm_x4(uint32_t* r, uint32_t addr) {
    asm volatile("ldmatrix.sync.aligned.m8n8.x4.shared.b16 {%0,%1,%2,%3}, [%4];"
                 : "=r"(r[0]), "=r"(r[1]), "=r"(r[2]), "=r"(r[3]) : "r"(addr));
}

__device__ __forceinline__ void mma_f16(float* c, const uint32_t* a, const uint32_t* b) {
    asm volatile(
        "mma.sync.aligned.m16n8k16.row.col.f32.f16.f16.f32 "
        "{%0,%1,%2,%3}, {%4,%5,%6,%7}, {%8,%9}, {%0,%1,%2,%3};"
        : "+f"(c[0]), "+f"(c[1]), "+f"(c[2]), "+f"(c[3])
        : "r"(a[0]), "r"(a[1]), "r"(a[2]), "r"(a[3]), "r"(b[0]), "r"(b[1]));
}

__device__ __forceinline__ __half2 tanh_h2(__half2 x) {
    uint32_t xi = *(uint32_t*)&x, r;
    asm("tanh.approx.f16x2 %0, %1;" : "=r"(r) : "r"(xi));
    return *(__half2*)&r;
}

__device__ __forceinline__ uint32_t h2bits(__half2 h) { return *(uint32_t*)&h; }

// ---------------------------------------------------------------------------
// Tensor-core projection GEMM via mma.sync fp16 hi/lo split (2-MMA emu):
//   D = Ah*Bh + Al*Bh   (drops Ah*Bl ~2.8e-4 rel, under error budget)
// z=0: Q*W1 -> g_qph (row-major, half2-packed over a).
// z=1: K*W2 -> g_kp4 ([a/8][bt] uint4-packed groups of 8 a's).
// ---------------------------------------------------------------------------
#define BM 128
#define BN 64
#define BK 64
#define RS 72                    // smem row stride in fp16 (144 B)
#define A_TILE_B  (BM * RS * 2)  // 18432
#define B_TILE_B  (BN * RS * 2)  //  9216
#define STAGE_B   (2 * A_TILE_B + B_TILE_B)   // Ah, Al, Bh = 46080
#define OFF_AH 0
#define OFF_AL A_TILE_B
#define OFF_BH (2 * A_TILE_B)
#define SMEM_DYN (2 * STAGE_B)   // 92160

extern __shared__ char dynsmem[];

__global__ __launch_bounds__(256, 1) void proj_tc_kernel(
    const float* __restrict__ Qin, const float* __restrict__ Kin,
    const float* __restrict__ W1,  const float* __restrict__ W2)
{
    const int z  = blockIdx.z;
    const float* X = z ? Kin : Qin;
    const float* W = z ? W2  : W1;
    const int m0 = blockIdx.y * BM;
    const int n0 = blockIdx.x * BN;

    const int tid  = threadIdx.x;
    const int wid  = tid >> 5;
    const int lane = tid & 31;
    const int wm   = wid >> 1;        // 0..3
    const int wn   = wid & 1;         // 0..1

    const uint32_t sbase = cvta_shared_u32(dynsmem);

    const int a_row = (lane & 7) + ((lane >> 3) & 1) * 8;   // 0..15
    const int a_kof = (lane >> 4) * 8;                      // 0 / 8
    const int b_row = (lane & 7) + ((lane >> 4) & 1) * 8;
    const int b_kof = ((lane >> 3) & 1) * 8;

    float acc[2][4][4] = {};   // [mi][nf][4]

    float4 va[8], vb[4];

    auto load_regs = [&](int ch) {
        const int k0 = ch * BK;
        #pragma unroll
        for (int i = 0; i < 8; i++) {
            const int idx = tid + i * 256;
            const int row = idx >> 4;
            const int c4  = (idx & 15) * 4;
            va[i] = *(const float4*)(X + (size_t)(m0 + row) * ND + k0 + c4);
        }
        #pragma unroll
        for (int i = 0; i < 4; i++) {
            const int idx = tid + i * 256;
            const int row = idx >> 4;
            const int c4  = (idx & 15) * 4;
            vb[i] = *(const float4*)(W + (size_t)(n0 + row) * ND + k0 + c4);
        }
    };

    auto store_smem = [&](int s) {
        char* st = dynsmem + s * STAGE_B;
        #pragma unroll
        for (int i = 0; i < 8; i++) {
            const int idx = tid + i * 256;
            const int row = idx >> 4;
            const int c4  = idx & 15;
            const uint32_t off = (uint32_t)(row * (RS * 2) + c4 * 8);
            __half2 h01 = __floats2half2_rn(va[i].x, va[i].y);
            __half2 h23 = __floats2half2_rn(va[i].z, va[i].w);
            float lx = va[i].x - __half2float(__low2half(h01));
            float ly = va[i].y - __half2float(__high2half(h01));
            float lz = va[i].z - __half2float(__low2half(h23));
            float lw = va[i].w - __half2float(__high2half(h23));
            *(uint2*)(st + OFF_AH + off) = make_uint2(h2bits(h01), h2bits(h23));
            *(uint2*)(st + OFF_AL + off) =
                make_uint2(h2bits(__floats2half2_rn(lx, ly)),
                           h2bits(__floats2half2_rn(lz, lw)));
        }
        #pragma unroll
        for (int i = 0; i < 4; i++) {
            const int idx = tid + i * 256;
            const int row = idx >> 4;
            const int c4  = idx & 15;
            const uint32_t off = (uint32_t)(row * (RS * 2) + c4 * 8);
            __half2 h01 = __floats2half2_rn(vb[i].x, vb[i].y);
            __half2 h23 = __floats2half2_rn(vb[i].z, vb[i].w);
            *(uint2*)(st + OFF_BH + off) = make_uint2(h2bits(h01), h2bits(h23));
        }
    };

    auto compute = [&](int s) {
        const uint32_t st = sbase + (uint32_t)(s * STAGE_B);
        #pragma unroll
        for (int ks = 0; ks < 4; ks++) {
            const uint32_t kb = (uint32_t)(ks * 16 * 2);
            uint32_t ah[2][4], al[2][4], bh[4][2];
            #pragma unroll
            for (int mi = 0; mi < 2; mi++) {
                const uint32_t ra = st + (uint32_t)((wm * 32 + mi * 16 + a_row) * (RS * 2))
                                   + kb + (uint32_t)(a_kof * 2);
                ldsm_x4(ah[mi], ra + OFF_AH);
                ldsm_x4(al[mi], ra + OFF_AL);
            }
            #pragma unroll
            for (int bi = 0; bi < 2; bi++) {
                const uint32_t rb = st + (uint32_t)((wn * 32 + bi * 16 + b_row) * (RS * 2))
                                   + kb + (uint32_t)(b_kof * 2);
                uint32_t t0[4];
                ldsm_x4(t0, rb + OFF_BH);
                bh[bi*2+0][0] = t0[0]; bh[bi*2+0][1] = t0[1];
                bh[bi*2+1][0] = t0[2]; bh[bi*2+1][1] = t0[3];
            }
            #pragma unroll
            for (int mi = 0; mi < 2; mi++)
                #pragma unroll
                for (int nf = 0; nf < 4; nf++) {
                    mma_f16(acc[mi][nf], ah[mi], bh[nf]);
                    mma_f16(acc[mi][nf], al[mi], bh[nf]);
                }
        }
    };

    load_regs(0);
    store_smem(0);
    __syncthreads();

    for (int ch = 0; ch < 16; ch++) {
        const int s = ch & 1;
        if (ch < 15) load_regs(ch + 1);
        compute(s);
        if (ch < 15) store_smem(s ^ 1);
        __syncthreads();
    }

    // -------- Epilogue: stage 128x64 fp32 tile in smem (stride 65) --------
    float* ep = (float*)dynsmem;
    #pragma unroll
    for (int mi = 0; mi < 2; mi++)
        #pragma unroll
        for (int nf = 0; nf < 4; nf++)
            #pragma unroll
            for (int j = 0; j < 4; j++) {
                const int r = wm * 32 + mi * 16 + (lane >> 2) + (j >> 1) * 8;
                const int c = wn * 32 + nf * 8 + (lane & 3) * 2 + (j & 1);
                ep[r * 65 + c] = acc[mi][nf][j];
            }
    __syncthreads();

    if (z == 0) {
        #pragma unroll
        for (int i = 0; i < 16; i++) {
            const int idx = tid + i * 256;    // 0..4095
            const int row = idx >> 5;         // 0..127
            const int c2  = idx & 31;         // 0..31
            __half2 h = __floats2half2_rn(ep[row * 65 + 2 * c2],
                                          ep[row * 65 + 2 * c2 + 1]);
            g_qph[(size_t)(m0 + row) * (NA / 2) + (n0 >> 1) + c2] = h;
        }
    } else {
        #pragma unroll
        for (int i = 0; i < 4; i++) {
            const int idx = tid + i * 256;    // 0..1023
            const int m   = idx & 127;        // 0..127
            const int gg  = idx >> 7;         // 0..7
            const float* row = &ep[m * 65 + 8 * gg];
            __half2 h0 = __floats2half2_rn(row[0], row[1]);
            __half2 h1 = __floats2half2_rn(row[2], row[3]);
            __half2 h2 = __floats2half2_rn(row[4], row[5]);
            __half2 h3 = __floats2half2_rn(row[6], row[7]);
            uint4 v;
            v.x = h2bits(h0); v.y = h2bits(h1);
            v.z = h2bits(h2); v.w = h2bits(h3);
            g_kp4[(size_t)((n0 >> 3) + gg) * (NB * NTK) + m0 + m] = v;
        }
    }
}

// ---------------------------------------------------------------------------
// Fused score + masked softmax, v8: mask compaction + balanced work units.
// CTA = (b, 4 q rows), 512 threads, grid 256.
// Work unit = (active pair, a-quarter of 128 a's); ~2048 units over 512
// threads = ~4 balanced passes (v7's 2x straggler removed). Lanes 4k..4k+3
// handle the 4 chunks of one pair; partials combine via shfl_xor(1,2);
// chunk-0 lane scatters into sc_s (pre-set -1e10). Softmax unchanged.
// ---------------------------------------------------------------------------
#define KSTRIDE (NB * NTK)      // uint4 elements between a-groups

__global__ __launch_bounds__(512, 2) void score_kernel(
    const int* __restrict__ mask, const float* __restrict__ w3,
    float* __restrict__ out)
{
    __shared__ __align__(16) uint4 qp4s[4][NA / 8];   // [q][64]
    __shared__ __align__(16) uint4 w34[NA / 8];
    __shared__ float sc_s[4][NTK];
    __shared__ short idx_s[4][NTK];
    __shared__ int   wcnt[4][8], wbase[4][8], qoff[5];
    __shared__ float redm[4][8], reds[4][8];

    const int tid  = threadIdx.x;
    const int t2   = tid & 255;
    const int wh   = tid >> 8;              // 0: q{0,1}, 1: q{2,3}
    const int wrp  = (tid >> 5) & 7;
    const int lane = tid & 31;
    const int item = blockIdx.x;            // 0..255
    const int b    = item >> 6;
    const int q0   = (item & 63) * 4;

    // stage qp rows + w3 (first 256 threads)
    if (tid < 256) {
        ((__half2*)w34)[tid] = __floats2half2_rn(w3[2 * tid], w3[2 * tid + 1]);
        const int q = tid >> 6, g = tid & 63;
        qp4s[q][g] = ((const uint4*)g_qph)[(size_t)(b * NTQ + q0 + q) * 64 + g];
    }

    // ---- mask ballot-compaction: warps 0-7 handle q0,q1; 8-15 handle q2,q3
    const int qa = 2 * wh, qb = 2 * wh + 1;
    const int mva = mask[((size_t)b * NTQ + q0 + qa) * NTK + t2];
    const int mvb = mask[((size_t)b * NTQ + q0 + qb) * NTK + t2];
    const unsigned bala = __ballot_sync(0xffffffffu, mva != 0);
    const unsigned balb = __ballot_sync(0xffffffffu, mvb != 0);
    if (lane == 0) { wcnt[qa][wrp] = __popc(bala); wcnt[qb][wrp] = __popc(balb); }
    const int posa = __popc(bala & ((1u << lane) - 1));
    const int posb = __popc(balb & ((1u << lane) - 1));

    // init score tile to -1e10 (1024 entries, 2 per thread)
    ((float*)sc_s)[tid]       = -1e10f;
    ((float*)sc_s)[tid + 512] = -1e10f;
    __syncthreads();

    if (tid == 0) {
        int s = 0;
        #pragma unroll
        for (int q = 0; q < 4; q++) {
            qoff[q] = s;
            #pragma unroll
            for (int w = 0; w < 8; w++) { wbase[q][w] = s; s += wcnt[q][w]; }
        }
        qoff[4] = s;
    }
    __syncthreads();

    if (mva) idx_s[qa][wbase[qa][wrp] - qoff[qa] + posa] = (short)t2;
    if (mvb) idx_s[qb][wbase[qb][wrp] - qoff[qb] + posb] = (short)t2;
    __syncthreads();

    const int total  = qoff[4];
    const int o1 = qoff[1], o2 = qoff[2], o3 = qoff[3];
    const int units  = total * 4;
    const int passes = (units + 511) >> 9;

    for (int p = 0; p < passes; p++) {
        const int u     = tid + (p << 9);
        const bool valid = (u < units);
        const int pr = valid ? (u >> 2) : 0;     // clamp: idx_s[0][0] exists
        const int c  = u & 3;                    // a-quarter 0..3
        const int q  = (pr >= o1) + (pr >= o2) + (pr >= o3);
        const int t  = idx_s[q][pr - qoff[q]];
        const uint4* gk = g_kp4 + (size_t)(c * 16) * KSTRIDE + (size_t)b * NTK + t;

        float acc = 0.f;
        uint4 kc0 = __ldg(gk);
        uint4 kc1 = __ldg(gk + KSTRIDE);

        #pragma unroll
        for (int jj = 0; jj < 8; jj++) {
            uint4 kn0, kn1;
            if (jj < 7) {
                kn0 = __ldg(gk + (size_t)(2 * jj + 2) * KSTRIDE);
                kn1 = __ldg(gk + (size_t)(2 * jj + 3) * KSTRIDE);
            }
            const int base = c * 16 + 2 * jj;
            uint4 uw0 = w34[base], uw1 = w34[base + 1];
            uint4 uq0 = qp4s[q][base], uq1 = qp4s[q][base + 1];
            const uint32_t* w0 = (const uint32_t*)&uw0;
            const uint32_t* w1 = (const uint32_t*)&uw1;
            const uint32_t* qv0 = (const uint32_t*)&uq0;
            const uint32_t* qv1 = (const uint32_t*)&uq1;
            const uint32_t* k0 = (const uint32_t*)&kc0;
            const uint32_t* k1 = (const uint32_t*)&kc1;

            // 4 independent half2 accumulators (short dep chains)
            __half2 aA = __floats2half2_rn(0.f, 0.f);
            __half2 aB = aA, aC = aA, aD = aA;
            {
                __half2 t0 = tanh_h2(__hadd2(*(__half2*)&qv0[0], *(__half2*)&k0[0]));
                __half2 t1 = tanh_h2(__hadd2(*(__half2*)&qv0[1], *(__half2*)&k0[1]));
                __half2 t2_ = tanh_h2(__hadd2(*(__half2*)&qv0[2], *(__half2*)&k0[2]));
                __half2 t3 = tanh_h2(__hadd2(*(__half2*)&qv0[3], *(__half2*)&k0[3]));
                aA = __hfma2(*(__half2*)&w0[0], t0, aA);
                aB = __hfma2(*(__half2*)&w0[1], t1, aB);
                aC = __hfma2(*(__half2*)&w0[2], t2_, aC);
                aD = __hfma2(*(__half2*)&w0[3], t3, aD);
            }
            {
                __half2 t0 = tanh_h2(__hadd2(*(__half2*)&qv1[0], *(__half2*)&k1[0]));
                __half2 t1 = tanh_h2(__hadd2(*(__half2*)&qv1[1], *(__half2*)&k1[1]));
                __half2 t2_ = tanh_h2(__hadd2(*(__half2*)&qv1[2], *(__half2*)&k1[2]));
                __half2 t3 = tanh_h2(__hadd2(*(__half2*)&qv1[3], *(__half2*)&k1[3]));
                aA = __hfma2(*(__half2*)&w1[0], t0, aA);
                aB = __hfma2(*(__half2*)&w1[1], t1, aB);
                aC = __hfma2(*(__half2*)&w1[2], t2_, aC);
                aD = __hfma2(*(__half2*)&w1[3], t3, aD);
            }
            __half2 hs = __hadd2(__hadd2(aA, aB), __hadd2(aC, aD));
            acc += __low2float(hs) + __high2float(hs);

            if (jj < 7) { kc0 = kn0; kc1 = kn1; }
        }

        if (!valid) acc = 0.f;
        // combine the 4 a-quarters of this pair (lanes 4k..4k+3)
        acc += __shfl_xor_sync(0xffffffffu, acc, 1);
        acc += __shfl_xor_sync(0xffffffffu, acc, 2);
        if (valid && c == 0) sc_s[q][t] = acc;
    }
    __syncthreads();

    // ---- softmax over t (first 256 threads; masked slots hold -1e10)
    float sc[4], ex[4];
    if (tid < 256) {
        #pragma unroll
        for (int q = 0; q < 4; q++) {
            sc[q] = sc_s[q][t2];
            float v = sc[q];
            #pragma unroll
            for (int o = 16; o; o >>= 1) v = fmaxf(v, __shfl_xor_sync(0xffffffffu, v, o));
            if (lane == 0) redm[q][wrp] = v;
        }
    }
    __syncthreads();

    if (tid < 256) {
        #pragma unroll
        for (int q = 0; q < 4; q++) {
            float m = redm[q][0];
            #pragma unroll
            for (int w = 1; w < 8; w++) m = fmaxf(m, redm[q][w]);
            ex[q] = exp2f((sc[q] - m) * 1.4426950408889634f);
            float v = ex[q];
            #pragma unroll
            for (int o = 16; o; o >>= 1) v += __shfl_xor_sync(0xffffffffu, v, o);
            if (lane == 0) reds[q][wrp] = v;
        }
    }
    __syncthreads();

    if (tid < 256) {
        #pragma unroll
        for (int q = 0; q < 4; q++) {
            float s = reds[q][0];
            #pragma unroll
            for (int w = 1; w < 8; w++) s += reds[q][w];
            out[((size_t)b * NTQ + q0 + q) * NTK + t2] = ex[q] * __frcp_rn(s);
        }
    }
}

// ---------------------------------------------------------------------------
extern "C" void kernel_launch(void* const* d_in, const int* in_sizes, int n_in,
                              void* d_out, int out_size)
{
    const float* Q    = (const float*)d_in[0];
    const float* K    = (const float*)d_in[1];
    const int*   mask = (const int*)d_in[2];
    const float* W1   = (const float*)d_in[3];
    const float* W2   = (const float*)d_in[4];
    const float* w3   = (const float*)d_in[5];
    float*       out  = (float*)d_out;

    cudaFuncSetAttribute(proj_tc_kernel,
                         cudaFuncAttributeMaxDynamicSharedMemorySize, SMEM_DYN);

    dim3 gp(NA / BN, (NB * NTQ) / BM, 2);   // 8 x 8 x 2 = 128 CTAs
    proj_tc_kernel<<<gp, 256, SMEM_DYN>>>(Q, K, W1, W2);

    score_kernel<<<NB * NTQ / 4, 512>>>(mask, w3, out);   // 256 CTAs, one wave
}

// round 13
// speedup vs baseline: 1.9307x; 1.9307x over previous
#include <cuda_runtime.h>
#include <cuda_fp16.h>
#include <cstdint>
#include <cstddef>

// Problem constants
#define NB   4
#define NTQ  256
#define NTK  256
#define ND   1024
#define NA   512

// Scratch (allocation-free rule: __device__ globals).
__device__ __half2 g_qph[NB * NTQ * (NA / 2)];     // [b*TQ+q][a/2]
__device__ uint4   g_kp4[(NA / 8) * NB * NTK];     // [a/8][b*TK+t] : 4x half2

// ---------------------------------------------------------------------------
// Helpers
// ---------------------------------------------------------------------------
__device__ __forceinline__ uint32_t cvta_shared_u32(const void* p) {
    uint32_t a;
    asm("{ .reg .u64 t; cvta.to.shared.u64 t, %1; cvt.u32.u64 %0, t; }"
        : "=r"(a) : "l"(p));
    return a;
}

__device__ __forceinline__ void ldsm_x4(uint32_t* r, uint32_t addr) {
    asm volatile("ldmatrix.sync.aligned.m8n8.x4.shared.b16 {%0,%1,%2,%3}, [%4];"
                 : "=r"(r[0]), "=r"(r[1]), "=r"(r[2]), "=r"(r[3]) : "r"(addr));
}

__device__ __forceinline__ void mma_f16(float* c, const uint32_t* a, const uint32_t* b) {
    asm volatile(
        "mma.sync.aligned.m16n8k16.row.col.f32.f16.f16.f32 "
        "{%0,%1,%2,%3}, {%4,%5,%6,%7}, {%8,%9}, {%0,%1,%2,%3};"
        : "+f"(c[0]), "+f"(c[1]), "+f"(c[2]), "+f"(c[3])
        : "r"(a[0]), "r"(a[1]), "r"(a[2]), "r"(a[3]), "r"(b[0]), "r"(b[1]));
}

__device__ __forceinline__ __half2 tanh_h2(__half2 x) {
    uint32_t xi = *(uint32_t*)&x, r;
    asm("tanh.approx.f16x2 %0, %1;" : "=r"(r) : "r"(xi));
    return *(__half2*)&r;
}

__device__ __forceinline__ uint32_t h2bits(__half2 h) { return *(uint32_t*)&h; }

// ---------------------------------------------------------------------------
// Tensor-core projection GEMM via mma.sync fp16 hi/lo split (2-MMA emu):
//   D = Ah*Bh + Al*Bh
// z=0: Q*W1 -> g_qph (row-major, half2-packed over a).
// z=1: K*W2 -> g_kp4 ([a/8][bt] uint4-packed groups of 8 a's).
// ---------------------------------------------------------------------------
#define BM 128
#define BN 64
#define BK 64
#define RS 72                    // smem row stride in fp16 (144 B)
#define A_TILE_B  (BM * RS * 2)  // 18432
#define B_TILE_B  (BN * RS * 2)  //  9216
#define STAGE_B   (2 * A_TILE_B + B_TILE_B)   // Ah, Al, Bh = 46080
#define OFF_AH 0
#define OFF_AL A_TILE_B
#define OFF_BH (2 * A_TILE_B)
#define SMEM_DYN (2 * STAGE_B)   // 92160

extern __shared__ char dynsmem[];

__global__ __launch_bounds__(256, 1) void proj_tc_kernel(
    const float* __restrict__ Qin, const float* __restrict__ Kin,
    const float* __restrict__ W1,  const float* __restrict__ W2)
{
    const int z  = blockIdx.z;
    const float* X = z ? Kin : Qin;
    const float* W = z ? W2  : W1;
    const int m0 = blockIdx.y * BM;
    const int n0 = blockIdx.x * BN;

    const int tid  = threadIdx.x;
    const int wid  = tid >> 5;
    const int lane = tid & 31;
    const int wm   = wid >> 1;        // 0..3
    const int wn   = wid & 1;         // 0..1

    const uint32_t sbase = cvta_shared_u32(dynsmem);

    const int a_row = (lane & 7) + ((lane >> 3) & 1) * 8;   // 0..15
    const int a_kof = (lane >> 4) * 8;                      // 0 / 8
    const int b_row = (lane & 7) + ((lane >> 4) & 1) * 8;
    const int b_kof = ((lane >> 3) & 1) * 8;

    float acc[2][4][4] = {};   // [mi][nf][4]

    float4 va[8], vb[4];

    auto load_regs = [&](int ch) {
        const int k0 = ch * BK;
        #pragma unroll
        for (int i = 0; i < 8; i++) {
            const int idx = tid + i * 256;
            const int row = idx >> 4;
            const int c4  = (idx & 15) * 4;
            va[i] = *(const float4*)(X + (size_t)(m0 + row) * ND + k0 + c4);
        }
        #pragma unroll
        for (int i = 0; i < 4; i++) {
            const int idx = tid + i * 256;
            const int row = idx >> 4;
            const int c4  = (idx & 15) * 4;
            vb[i] = *(const float4*)(W + (size_t)(n0 + row) * ND + k0 + c4);
        }
    };

    auto store_smem = [&](int s) {
        char* st = dynsmem + s * STAGE_B;
        #pragma unroll
        for (int i = 0; i < 8; i++) {
            const int idx = tid + i * 256;
            const int row = idx >> 4;
            const int c4  = idx & 15;
            const uint32_t off = (uint32_t)(row * (RS * 2) + c4 * 8);
            __half2 h01 = __floats2half2_rn(va[i].x, va[i].y);
            __half2 h23 = __floats2half2_rn(va[i].z, va[i].w);
            float lx = va[i].x - __half2float(__low2half(h01));
            float ly = va[i].y - __half2float(__high2half(h01));
            float lz = va[i].z - __half2float(__low2half(h23));
            float lw = va[i].w - __half2float(__high2half(h23));
            *(uint2*)(st + OFF_AH + off) = make_uint2(h2bits(h01), h2bits(h23));
            *(uint2*)(st + OFF_AL + off) =
                make_uint2(h2bits(__floats2half2_rn(lx, ly)),
                           h2bits(__floats2half2_rn(lz, lw)));
        }
        #pragma unroll
        for (int i = 0; i < 4; i++) {
            const int idx = tid + i * 256;
            const int row = idx >> 4;
            const int c4  = idx & 15;
            const uint32_t off = (uint32_t)(row * (RS * 2) + c4 * 8);
            __half2 h01 = __floats2half2_rn(vb[i].x, vb[i].y);
            __half2 h23 = __floats2half2_rn(vb[i].z, vb[i].w);
            *(uint2*)(st + OFF_BH + off) = make_uint2(h2bits(h01), h2bits(h23));
        }
    };

    auto compute = [&](int s) {
        const uint32_t st = sbase + (uint32_t)(s * STAGE_B);
        #pragma unroll
        for (int ks = 0; ks < 4; ks++) {
            const uint32_t kb = (uint32_t)(ks * 16 * 2);
            uint32_t ah[2][4], al[2][4], bh[4][2];
            #pragma unroll
            for (int mi = 0; mi < 2; mi++) {
                const uint32_t ra = st + (uint32_t)((wm * 32 + mi * 16 + a_row) * (RS * 2))
                                   + kb + (uint32_t)(a_kof * 2);
                ldsm_x4(ah[mi], ra + OFF_AH);
                ldsm_x4(al[mi], ra + OFF_AL);
            }
            #pragma unroll
            for (int bi = 0; bi < 2; bi++) {
                const uint32_t rb = st + (uint32_t)((wn * 32 + bi * 16 + b_row) * (RS * 2))
                                   + kb + (uint32_t)(b_kof * 2);
                uint32_t t0[4];
                ldsm_x4(t0, rb + OFF_BH);
                bh[bi*2+0][0] = t0[0]; bh[bi*2+0][1] = t0[1];
                bh[bi*2+1][0] = t0[2]; bh[bi*2+1][1] = t0[3];
            }
            #pragma unroll
            for (int mi = 0; mi < 2; mi++)
                #pragma unroll
                for (int nf = 0; nf < 4; nf++) {
                    mma_f16(acc[mi][nf], ah[mi], bh[nf]);
                    mma_f16(acc[mi][nf], al[mi], bh[nf]);
                }
        }
    };

    load_regs(0);
    store_smem(0);
    __syncthreads();

    for (int ch = 0; ch < 16; ch++) {
        const int s = ch & 1;
        if (ch < 15) load_regs(ch + 1);
        compute(s);
        if (ch < 15) store_smem(s ^ 1);
        __syncthreads();
    }

    // -------- Epilogue: stage 128x64 fp32 tile in smem (stride 65) --------
    float* ep = (float*)dynsmem;
    #pragma unroll
    for (int mi = 0; mi < 2; mi++)
        #pragma unroll
        for (int nf = 0; nf < 4; nf++)
            #pragma unroll
            for (int j = 0; j < 4; j++) {
                const int r = wm * 32 + mi * 16 + (lane >> 2) + (j >> 1) * 8;
                const int c = wn * 32 + nf * 8 + (lane & 3) * 2 + (j & 1);
                ep[r * 65 + c] = acc[mi][nf][j];
            }
    __syncthreads();

    if (z == 0) {
        #pragma unroll
        for (int i = 0; i < 16; i++) {
            const int idx = tid + i * 256;    // 0..4095
            const int row = idx >> 5;         // 0..127
            const int c2  = idx & 31;         // 0..31
            __half2 h = __floats2half2_rn(ep[row * 65 + 2 * c2],
                                          ep[row * 65 + 2 * c2 + 1]);
            g_qph[(size_t)(m0 + row) * (NA / 2) + (n0 >> 1) + c2] = h;
        }
    } else {
        #pragma unroll
        for (int i = 0; i < 4; i++) {
            const int idx = tid + i * 256;    // 0..1023
            const int m   = idx & 127;        // 0..127
            const int gg  = idx >> 7;         // 0..7
            const float* row = &ep[m * 65 + 8 * gg];
            __half2 h0 = __floats2half2_rn(row[0], row[1]);
            __half2 h1 = __floats2half2_rn(row[2], row[3]);
            __half2 h2 = __floats2half2_rn(row[4], row[5]);
            __half2 h3 = __floats2half2_rn(row[6], row[7]);
            uint4 v;
            v.x = h2bits(h0); v.y = h2bits(h1);
            v.z = h2bits(h2); v.w = h2bits(h3);
            g_kp4[(size_t)((n0 >> 3) + gg) * (NB * NTK) + m0 + m] = v;
        }
    }
}

// ---------------------------------------------------------------------------
// Fused score + masked softmax, v9: mask compaction + CHUNK-MAJOR balanced
// work units. Unit u in [0, 4*total): c = u/total (a-quarter), pair = u-c*total.
// Consecutive threads -> consecutive pairs, SAME chunk => coalescing of v7
// with straggler quanta of 1/4 pair. Chunk partials atomicAdd into smem
// accumulator tile (init 0); mask applied from stored ballots at softmax.
// ---------------------------------------------------------------------------
#define KSTRIDE (NB * NTK)      // uint4 elements between a-groups

__global__ __launch_bounds__(512, 2) void score_kernel(
    const int* __restrict__ mask, const float* __restrict__ w3,
    float* __restrict__ out)
{
    __shared__ __align__(16) uint4 qp4s[4][NA / 8];   // [q][64]
    __shared__ __align__(16) uint4 w34[NA / 8];
    __shared__ float acc_s[4][NTK];
    __shared__ short idx_s[4][NTK];
    __shared__ unsigned ball_s[4][8];
    __shared__ int   wcnt[4][8], wbase[4][8], qoff[5];
    __shared__ float redm[4][8], reds[4][8];

    const int tid  = threadIdx.x;
    const int t2   = tid & 255;
    const int wh   = tid >> 8;              // 0: q{0,1}, 1: q{2,3}
    const int wrp  = (tid >> 5) & 7;
    const int lane = tid & 31;
    const int item = blockIdx.x;            // 0..255
    const int b    = item >> 6;
    const int q0   = (item & 63) * 4;

    // stage qp rows + w3 (first 256 threads)
    if (tid < 256) {
        ((__half2*)w34)[tid] = __floats2half2_rn(w3[2 * tid], w3[2 * tid + 1]);
        const int q = tid >> 6, g = tid & 63;
        qp4s[q][g] = ((const uint4*)g_qph)[(size_t)(b * NTQ + q0 + q) * 64 + g];
    }

    // ---- mask ballot-compaction: warps 0-7 handle q0,q1; 8-15 handle q2,q3
    const int qa = 2 * wh, qb = 2 * wh + 1;
    const int mva = mask[((size_t)b * NTQ + q0 + qa) * NTK + t2];
    const int mvb = mask[((size_t)b * NTQ + q0 + qb) * NTK + t2];
    const unsigned bala = __ballot_sync(0xffffffffu, mva != 0);
    const unsigned balb = __ballot_sync(0xffffffffu, mvb != 0);
    if (lane == 0) {
        wcnt[qa][wrp] = __popc(bala); wcnt[qb][wrp] = __popc(balb);
        ball_s[qa][wrp] = bala;       ball_s[qb][wrp] = balb;
    }
    const int posa = __popc(bala & ((1u << lane) - 1));
    const int posb = __popc(balb & ((1u << lane) - 1));

    // init accumulator tile to 0 (1024 entries, 2 per thread)
    ((float*)acc_s)[tid]       = 0.f;
    ((float*)acc_s)[tid + 512] = 0.f;
    __syncthreads();

    if (tid == 0) {
        int s = 0;
        #pragma unroll
        for (int q = 0; q < 4; q++) {
            qoff[q] = s;
            #pragma unroll
            for (int w = 0; w < 8; w++) { wbase[q][w] = s; s += wcnt[q][w]; }
        }
        qoff[4] = s;
    }
    __syncthreads();

    if (mva) idx_s[qa][wbase[qa][wrp] - qoff[qa] + posa] = (short)t2;
    if (mvb) idx_s[qb][wbase[qb][wrp] - qoff[qb] + posb] = (short)t2;
    __syncthreads();

    const int total = qoff[4];
    const int o1 = qoff[1], o2 = qoff[2], o3 = qoff[3];
    const int units = total * 4;

    for (int u = tid; u < units; u += 512) {
        // chunk-major decode: first `total` units are chunk 0, etc.
        int c = 0, pr = u;
        if (pr >= total) { c++; pr -= total; }
        if (pr >= total) { c++; pr -= total; }
        if (pr >= total) { c++; pr -= total; }
        const int q = (pr >= o1) + (pr >= o2) + (pr >= o3);
        const int t = idx_s[q][pr - qoff[q]];
        const uint4* gk = g_kp4 + (size_t)(c * 16) * KSTRIDE + (size_t)b * NTK + t;

        float acc = 0.f;
        uint4 kc0 = __ldg(gk);
        uint4 kc1 = __ldg(gk + KSTRIDE);

        #pragma unroll
        for (int jj = 0; jj < 8; jj++) {
            uint4 kn0, kn1;
            if (jj < 7) {
                kn0 = __ldg(gk + (size_t)(2 * jj + 2) * KSTRIDE);
                kn1 = __ldg(gk + (size_t)(2 * jj + 3) * KSTRIDE);
            }
            const int base = c * 16 + 2 * jj;
            uint4 uw0 = w34[base], uw1 = w34[base + 1];
            uint4 uq0 = qp4s[q][base], uq1 = qp4s[q][base + 1];
            const uint32_t* w0 = (const uint32_t*)&uw0;
            const uint32_t* w1 = (const uint32_t*)&uw1;
            const uint32_t* qv0 = (const uint32_t*)&uq0;
            const uint32_t* qv1 = (const uint32_t*)&uq1;
            const uint32_t* k0 = (const uint32_t*)&kc0;
            const uint32_t* k1 = (const uint32_t*)&kc1;

            __half2 aA = __floats2half2_rn(0.f, 0.f);
            __half2 aB = aA, aC = aA, aD = aA;
            {
                __half2 t0 = tanh_h2(__hadd2(*(__half2*)&qv0[0], *(__half2*)&k0[0]));
                __half2 t1 = tanh_h2(__hadd2(*(__half2*)&qv0[1], *(__half2*)&k0[1]));
                __half2 t2_ = tanh_h2(__hadd2(*(__half2*)&qv0[2], *(__half2*)&k0[2]));
                __half2 t3 = tanh_h2(__hadd2(*(__half2*)&qv0[3], *(__half2*)&k0[3]));
                aA = __hfma2(*(__half2*)&w0[0], t0, aA);
                aB = __hfma2(*(__half2*)&w0[1], t1, aB);
                aC = __hfma2(*(__half2*)&w0[2], t2_, aC);
                aD = __hfma2(*(__half2*)&w0[3], t3, aD);
            }
            {
                __half2 t0 = tanh_h2(__hadd2(*(__half2*)&qv1[0], *(__half2*)&k1[0]));
                __half2 t1 = tanh_h2(__hadd2(*(__half2*)&qv1[1], *(__half2*)&k1[1]));
                __half2 t2_ = tanh_h2(__hadd2(*(__half2*)&qv1[2], *(__half2*)&k1[2]));
                __half2 t3 = tanh_h2(__hadd2(*(__half2*)&qv1[3], *(__half2*)&k1[3]));
                aA = __hfma2(*(__half2*)&w1[0], t0, aA);
                aB = __hfma2(*(__half2*)&w1[1], t1, aB);
                aC = __hfma2(*(__half2*)&w1[2], t2_, aC);
                aD = __hfma2(*(__half2*)&w1[3], t3, aD);
            }
            __half2 hs = __hadd2(__hadd2(aA, aB), __hadd2(aC, aD));
            acc += __low2float(hs) + __high2float(hs);

            if (jj < 7) { kc0 = kn0; kc1 = kn1; }
        }

        atomicAdd(&acc_s[q][t], acc);
    }
    __syncthreads();

    // ---- softmax over t (first 256 threads; mask applied from ballots)
    float sc[4], ex[4];
    if (tid < 256) {
        #pragma unroll
        for (int q = 0; q < 4; q++) {
            const unsigned bit = (ball_s[q][t2 >> 5] >> (t2 & 31)) & 1u;
            sc[q] = bit ? acc_s[q][t2] : -1e10f;
            float v = sc[q];
            #pragma unroll
            for (int o = 16; o; o >>= 1) v = fmaxf(v, __shfl_xor_sync(0xffffffffu, v, o));
            if (lane == 0) redm[q][wrp] = v;
        }
    }
    __syncthreads();

    if (tid < 256) {
        #pragma unroll
        for (int q = 0; q < 4; q++) {
            float m = redm[q][0];
            #pragma unroll
            for (int w = 1; w < 8; w++) m = fmaxf(m, redm[q][w]);
            ex[q] = exp2f((sc[q] - m) * 1.4426950408889634f);
            float v = ex[q];
            #pragma unroll
            for (int o = 16; o; o >>= 1) v += __shfl_xor_sync(0xffffffffu, v, o);
            if (lane == 0) reds[q][wrp] = v;
        }
    }
    __syncthreads();

    if (tid < 256) {
        #pragma unroll
        for (int q = 0; q < 4; q++) {
            float s = reds[q][0];
            #pragma unroll
            for (int w = 1; w < 8; w++) s += reds[q][w];
            out[((size_t)b * NTQ + q0 + q) * NTK + t2] = ex[q] * __frcp_rn(s);
        }
    }
}

// ---------------------------------------------------------------------------
extern "C" void kernel_launch(void* const* d_in, const int* in_sizes, int n_in,
                              void* d_out, int out_size)
{
    const float* Q    = (const float*)d_in[0];
    const float* K    = (const float*)d_in[1];
    const int*   mask = (const int*)d_in[2];
    const float* W1   = (const float*)d_in[3];
    const float* W2   = (const float*)d_in[4];
    const float* w3   = (const float*)d_in[5];
    float*       out  = (float*)d_out;

    cudaFuncSetAttribute(proj_tc_kernel,
                         cudaFuncAttributeMaxDynamicSharedMemorySize, SMEM_DYN);

    dim3 gp(NA / BN, (NB * NTQ) / BM, 2);   // 8 x 8 x 2 = 128 CTAs
    proj_tc_kernel<<<gp, 256, SMEM_DYN>>>(Q, K, W1, W2);

    score_kernel<<<NB * NTQ / 4, 512>>>(mask, w3, out);   // 256 CTAs, one wave
}

// round 14
// speedup vs baseline: 2.1906x; 1.1347x over previous
#include <cuda_runtime.h>
#include <cuda_fp16.h>
#include <cstdint>
#include <cstddef>

// Problem constants
#define NB   4
#define NTQ  256
#define NTK  256
#define ND   1024
#define NA   512

// Scratch (allocation-free rule: __device__ globals).
__device__ __half2 g_qph[NB * NTQ * (NA / 2)];     // [b*TQ+q][a/2]
__device__ uint4   g_kp4[(NA / 8) * NB * NTK];     // [a/8][b*TK+t] : 4x half2

// ---------------------------------------------------------------------------
// Helpers
// ---------------------------------------------------------------------------
__device__ __forceinline__ uint32_t cvta_shared_u32(const void* p) {
    uint32_t a;
    asm("{ .reg .u64 t; cvta.to.shared.u64 t, %1; cvt.u32.u64 %0, t; }"
        : "=r"(a) : "l"(p));
    return a;
}

__device__ __forceinline__ void ldsm_x4(uint32_t* r, uint32_t addr) {
    asm volatile("ldmatrix.sync.aligned.m8n8.x4.shared.b16 {%0,%1,%2,%3}, [%4];"
                 : "=r"(r[0]), "=r"(r[1]), "=r"(r[2]), "=r"(r[3]) : "r"(addr));
}

__device__ __forceinline__ void mma_f16(float* c, const uint32_t* a, const uint32_t* b) {
    asm volatile(
        "mma.sync.aligned.m16n8k16.row.col.f32.f16.f16.f32 "
        "{%0,%1,%2,%3}, {%4,%5,%6,%7}, {%8,%9}, {%0,%1,%2,%3};"
        : "+f"(c[0]), "+f"(c[1]), "+f"(c[2]), "+f"(c[3])
        : "r"(a[0]), "r"(a[1]), "r"(a[2]), "r"(a[3]), "r"(b[0]), "r"(b[1]));
}

__device__ __forceinline__ __half2 tanh_h2(__half2 x) {
    uint32_t xi = *(uint32_t*)&x, r;
    asm("tanh.approx.f16x2 %0, %1;" : "=r"(r) : "r"(xi));
    return *(__half2*)&r;
}

__device__ __forceinline__ uint32_t h2bits(__half2 h) { return *(uint32_t*)&h; }

// ---------------------------------------------------------------------------
// Tensor-core projection GEMM, plain fp16 mma.sync (fp32 accumulate).
// Input fp32 rounded to fp16 (error ~2.8e-4 rel on N(0,1) projections —
// inside budget per measured error ladder).
// z=0: Q*W1 -> g_qph (row-major, half2-packed over a).
// z=1: K*W2 -> g_kp4 ([a/8][bt] uint4-packed groups of 8 a's).
// ---------------------------------------------------------------------------
#define BM 128
#define BN 64
#define BK 64
#define RS 72                    // smem row stride in fp16 (144 B)
#define A_TILE_B  (BM * RS * 2)  // 18432
#define B_TILE_B  (BN * RS * 2)  //  9216
#define STAGE_B   (A_TILE_B + B_TILE_B)   // Ah, Bh = 27648
#define OFF_AH 0
#define OFF_BH A_TILE_B
#define SMEM_DYN (2 * STAGE_B)   // 55296

extern __shared__ char dynsmem[];

__global__ __launch_bounds__(256, 1) void proj_tc_kernel(
    const float* __restrict__ Qin, const float* __restrict__ Kin,
    const float* __restrict__ W1,  const float* __restrict__ W2)
{
    const int z  = blockIdx.z;
    const float* X = z ? Kin : Qin;
    const float* W = z ? W2  : W1;
    const int m0 = blockIdx.y * BM;
    const int n0 = blockIdx.x * BN;

    const int tid  = threadIdx.x;
    const int wid  = tid >> 5;
    const int lane = tid & 31;
    const int wm   = wid >> 1;        // 0..3
    const int wn   = wid & 1;         // 0..1

    const uint32_t sbase = cvta_shared_u32(dynsmem);

    const int a_row = (lane & 7) + ((lane >> 3) & 1) * 8;   // 0..15
    const int a_kof = (lane >> 4) * 8;                      // 0 / 8
    const int b_row = (lane & 7) + ((lane >> 4) & 1) * 8;
    const int b_kof = ((lane >> 3) & 1) * 8;

    float acc[2][4][4] = {};   // [mi][nf][4]

    float4 va[8], vb[4];

    auto load_regs = [&](int ch) {
        const int k0 = ch * BK;
        #pragma unroll
        for (int i = 0; i < 8; i++) {
            const int idx = tid + i * 256;
            const int row = idx >> 4;
            const int c4  = (idx & 15) * 4;
            va[i] = *(const float4*)(X + (size_t)(m0 + row) * ND + k0 + c4);
        }
        #pragma unroll
        for (int i = 0; i < 4; i++) {
            const int idx = tid + i * 256;
            const int row = idx >> 4;
            const int c4  = (idx & 15) * 4;
            vb[i] = *(const float4*)(W + (size_t)(n0 + row) * ND + k0 + c4);
        }
    };

    auto store_smem = [&](int s) {
        char* st = dynsmem + s * STAGE_B;
        #pragma unroll
        for (int i = 0; i < 8; i++) {
            const int idx = tid + i * 256;
            const int row = idx >> 4;
            const int c4  = idx & 15;
            const uint32_t off = (uint32_t)(row * (RS * 2) + c4 * 8);
            __half2 h01 = __floats2half2_rn(va[i].x, va[i].y);
            __half2 h23 = __floats2half2_rn(va[i].z, va[i].w);
            *(uint2*)(st + OFF_AH + off) = make_uint2(h2bits(h01), h2bits(h23));
        }
        #pragma unroll
        for (int i = 0; i < 4; i++) {
            const int idx = tid + i * 256;
            const int row = idx >> 4;
            const int c4  = idx & 15;
            const uint32_t off = (uint32_t)(row * (RS * 2) + c4 * 8);
            __half2 h01 = __floats2half2_rn(vb[i].x, vb[i].y);
            __half2 h23 = __floats2half2_rn(vb[i].z, vb[i].w);
            *(uint2*)(st + OFF_BH + off) = make_uint2(h2bits(h01), h2bits(h23));
        }
    };

    auto compute = [&](int s) {
        const uint32_t st = sbase + (uint32_t)(s * STAGE_B);
        #pragma unroll
        for (int ks = 0; ks < 4; ks++) {
            const uint32_t kb = (uint32_t)(ks * 16 * 2);
            uint32_t ah[2][4], bh[4][2];
            #pragma unroll
            for (int mi = 0; mi < 2; mi++) {
                const uint32_t ra = st + (uint32_t)((wm * 32 + mi * 16 + a_row) * (RS * 2))
                                   + kb + (uint32_t)(a_kof * 2);
                ldsm_x4(ah[mi], ra + OFF_AH);
            }
            #pragma unroll
            for (int bi = 0; bi < 2; bi++) {
                const uint32_t rb = st + (uint32_t)((wn * 32 + bi * 16 + b_row) * (RS * 2))
                                   + kb + (uint32_t)(b_kof * 2);
                uint32_t t0[4];
                ldsm_x4(t0, rb + OFF_BH);
                bh[bi*2+0][0] = t0[0]; bh[bi*2+0][1] = t0[1];
                bh[bi*2+1][0] = t0[2]; bh[bi*2+1][1] = t0[3];
            }
            #pragma unroll
            for (int mi = 0; mi < 2; mi++)
                #pragma unroll
                for (int nf = 0; nf < 4; nf++)
                    mma_f16(acc[mi][nf], ah[mi], bh[nf]);
        }
    };

    load_regs(0);
    store_smem(0);
    __syncthreads();

    for (int ch = 0; ch < 16; ch++) {
        const int s = ch & 1;
        if (ch < 15) load_regs(ch + 1);
        compute(s);
        if (ch < 15) store_smem(s ^ 1);
        __syncthreads();
    }

    // -------- Epilogue: stage 128x64 fp32 tile in smem (stride 65) --------
    float* ep = (float*)dynsmem;   // 33280 B < SMEM_DYN
    #pragma unroll
    for (int mi = 0; mi < 2; mi++)
        #pragma unroll
        for (int nf = 0; nf < 4; nf++)
            #pragma unroll
            for (int j = 0; j < 4; j++) {
                const int r = wm * 32 + mi * 16 + (lane >> 2) + (j >> 1) * 8;
                const int c = wn * 32 + nf * 8 + (lane & 3) * 2 + (j & 1);
                ep[r * 65 + c] = acc[mi][nf][j];
            }
    __syncthreads();

    if (z == 0) {
        #pragma unroll
        for (int i = 0; i < 16; i++) {
            const int idx = tid + i * 256;    // 0..4095
            const int row = idx >> 5;         // 0..127
            const int c2  = idx & 31;         // 0..31
            __half2 h = __floats2half2_rn(ep[row * 65 + 2 * c2],
                                          ep[row * 65 + 2 * c2 + 1]);
            g_qph[(size_t)(m0 + row) * (NA / 2) + (n0 >> 1) + c2] = h;
        }
    } else {
        #pragma unroll
        for (int i = 0; i < 4; i++) {
            const int idx = tid + i * 256;    // 0..1023
            const int m   = idx & 127;        // 0..127
            const int gg  = idx >> 7;         // 0..7
            const float* row = &ep[m * 65 + 8 * gg];
            __half2 h0 = __floats2half2_rn(row[0], row[1]);
            __half2 h1 = __floats2half2_rn(row[2], row[3]);
            __half2 h2 = __floats2half2_rn(row[4], row[5]);
            __half2 h3 = __floats2half2_rn(row[6], row[7]);
            uint4 v;
            v.x = h2bits(h0); v.y = h2bits(h1);
            v.z = h2bits(h2); v.w = h2bits(h3);
            g_kp4[(size_t)((n0 >> 3) + gg) * (NB * NTK) + m0 + m] = v;
        }
    }
}

// ---------------------------------------------------------------------------
// Fused score + masked softmax, v9 (UNCHANGED from best): mask compaction +
// chunk-major balanced work units + smem atomic combine.
// ---------------------------------------------------------------------------
#define KSTRIDE (NB * NTK)      // uint4 elements between a-groups

__global__ __launch_bounds__(512, 2) void score_kernel(
    const int* __restrict__ mask, const float* __restrict__ w3,
    float* __restrict__ out)
{
    __shared__ __align__(16) uint4 qp4s[4][NA / 8];   // [q][64]
    __shared__ __align__(16) uint4 w34[NA / 8];
    __shared__ float acc_s[4][NTK];
    __shared__ short idx_s[4][NTK];
    __shared__ unsigned ball_s[4][8];
    __shared__ int   wcnt[4][8], wbase[4][8], qoff[5];
    __shared__ float redm[4][8], reds[4][8];

    const int tid  = threadIdx.x;
    const int t2   = tid & 255;
    const int wh   = tid >> 8;              // 0: q{0,1}, 1: q{2,3}
    const int wrp  = (tid >> 5) & 7;
    const int lane = tid & 31;
    const int item = blockIdx.x;            // 0..255
    const int b    = item >> 6;
    const int q0   = (item & 63) * 4;

    // stage qp rows + w3 (first 256 threads)
    if (tid < 256) {
        ((__half2*)w34)[tid] = __floats2half2_rn(w3[2 * tid], w3[2 * tid + 1]);
        const int q = tid >> 6, g = tid & 63;
        qp4s[q][g] = ((const uint4*)g_qph)[(size_t)(b * NTQ + q0 + q) * 64 + g];
    }

    // ---- mask ballot-compaction: warps 0-7 handle q0,q1; 8-15 handle q2,q3
    const int qa = 2 * wh, qb = 2 * wh + 1;
    const int mva = mask[((size_t)b * NTQ + q0 + qa) * NTK + t2];
    const int mvb = mask[((size_t)b * NTQ + q0 + qb) * NTK + t2];
    const unsigned bala = __ballot_sync(0xffffffffu, mva != 0);
    const unsigned balb = __ballot_sync(0xffffffffu, mvb != 0);
    if (lane == 0) {
        wcnt[qa][wrp] = __popc(bala); wcnt[qb][wrp] = __popc(balb);
        ball_s[qa][wrp] = bala;       ball_s[qb][wrp] = balb;
    }
    const int posa = __popc(bala & ((1u << lane) - 1));
    const int posb = __popc(balb & ((1u << lane) - 1));

    // init accumulator tile to 0 (1024 entries, 2 per thread)
    ((float*)acc_s)[tid]       = 0.f;
    ((float*)acc_s)[tid + 512] = 0.f;
    __syncthreads();

    if (tid == 0) {
        int s = 0;
        #pragma unroll
        for (int q = 0; q < 4; q++) {
            qoff[q] = s;
            #pragma unroll
            for (int w = 0; w < 8; w++) { wbase[q][w] = s; s += wcnt[q][w]; }
        }
        qoff[4] = s;
    }
    __syncthreads();

    if (mva) idx_s[qa][wbase[qa][wrp] - qoff[qa] + posa] = (short)t2;
    if (mvb) idx_s[qb][wbase[qb][wrp] - qoff[qb] + posb] = (short)t2;
    __syncthreads();

    const int total = qoff[4];
    const int o1 = qoff[1], o2 = qoff[2], o3 = qoff[3];
    const int units = total * 4;

    for (int u = tid; u < units; u += 512) {
        // chunk-major decode: first `total` units are chunk 0, etc.
        int c = 0, pr = u;
        if (pr >= total) { c++; pr -= total; }
        if (pr >= total) { c++; pr -= total; }
        if (pr >= total) { c++; pr -= total; }
        const int q = (pr >= o1) + (pr >= o2) + (pr >= o3);
        const int t = idx_s[q][pr - qoff[q]];
        const uint4* gk = g_kp4 + (size_t)(c * 16) * KSTRIDE + (size_t)b * NTK + t;

        float acc = 0.f;
        uint4 kc0 = __ldg(gk);
        uint4 kc1 = __ldg(gk + KSTRIDE);

        #pragma unroll
        for (int jj = 0; jj < 8; jj++) {
            uint4 kn0, kn1;
            if (jj < 7) {
                kn0 = __ldg(gk + (size_t)(2 * jj + 2) * KSTRIDE);
                kn1 = __ldg(gk + (size_t)(2 * jj + 3) * KSTRIDE);
            }
            const int base = c * 16 + 2 * jj;
            uint4 uw0 = w34[base], uw1 = w34[base + 1];
            uint4 uq0 = qp4s[q][base], uq1 = qp4s[q][base + 1];
            const uint32_t* w0 = (const uint32_t*)&uw0;
            const uint32_t* w1 = (const uint32_t*)&uw1;
            const uint32_t* qv0 = (const uint32_t*)&uq0;
            const uint32_t* qv1 = (const uint32_t*)&uq1;
            const uint32_t* k0 = (const uint32_t*)&kc0;
            const uint32_t* k1 = (const uint32_t*)&kc1;

            __half2 aA = __floats2half2_rn(0.f, 0.f);
            __half2 aB = aA, aC = aA, aD = aA;
            {
                __half2 t0 = tanh_h2(__hadd2(*(__half2*)&qv0[0], *(__half2*)&k0[0]));
                __half2 t1 = tanh_h2(__hadd2(*(__half2*)&qv0[1], *(__half2*)&k0[1]));
                __half2 t2_ = tanh_h2(__hadd2(*(__half2*)&qv0[2], *(__half2*)&k0[2]));
                __half2 t3 = tanh_h2(__hadd2(*(__half2*)&qv0[3], *(__half2*)&k0[3]));
                aA = __hfma2(*(__half2*)&w0[0], t0, aA);
                aB = __hfma2(*(__half2*)&w0[1], t1, aB);
                aC = __hfma2(*(__half2*)&w0[2], t2_, aC);
                aD = __hfma2(*(__half2*)&w0[3], t3, aD);
            }
            {
                __half2 t0 = tanh_h2(__hadd2(*(__half2*)&qv1[0], *(__half2*)&k1[0]));
                __half2 t1 = tanh_h2(__hadd2(*(__half2*)&qv1[1], *(__half2*)&k1[1]));
                __half2 t2_ = tanh_h2(__hadd2(*(__half2*)&qv1[2], *(__half2*)&k1[2]));
                __half2 t3 = tanh_h2(__hadd2(*(__half2*)&qv1[3], *(__half2*)&k1[3]));
                aA = __hfma2(*(__half2*)&w1[0], t0, aA);
                aB = __hfma2(*(__half2*)&w1[1], t1, aB);
                aC = __hfma2(*(__half2*)&w1[2], t2_, aC);
                aD = __hfma2(*(__half2*)&w1[3], t3, aD);
            }
            __half2 hs = __hadd2(__hadd2(aA, aB), __hadd2(aC, aD));
            acc += __low2float(hs) + __high2float(hs);

            if (jj < 7) { kc0 = kn0; kc1 = kn1; }
        }

        atomicAdd(&acc_s[q][t], acc);
    }
    __syncthreads();

    // ---- softmax over t (first 256 threads; mask applied from ballots)
    float sc[4], ex[4];
    if (tid < 256) {
        #pragma unroll
        for (int q = 0; q < 4; q++) {
            const unsigned bit = (ball_s[q][t2 >> 5] >> (t2 & 31)) & 1u;
            sc[q] = bit ? acc_s[q][t2] : -1e10f;
            float v = sc[q];
            #pragma unroll
            for (int o = 16; o; o >>= 1) v = fmaxf(v, __shfl_xor_sync(0xffffffffu, v, o));
            if (lane == 0) redm[q][wrp] = v;
        }
    }
    __syncthreads();

    if (tid < 256) {
        #pragma unroll
        for (int q = 0; q < 4; q++) {
            float m = redm[q][0];
            #pragma unroll
            for (int w = 1; w < 8; w++) m = fmaxf(m, redm[q][w]);
            ex[q] = exp2f((sc[q] - m) * 1.4426950408889634f);
            float v = ex[q];
            #pragma unroll
            for (int o = 16; o; o >>= 1) v += __shfl_xor_sync(0xffffffffu, v, o);
            if (lane == 0) reds[q][wrp] = v;
        }
    }
    __syncthreads();

    if (tid < 256) {
        #pragma unroll
        for (int q = 0; q < 4; q++) {
            float s = reds[q][0];
            #pragma unroll
            for (int w = 1; w < 8; w++) s += reds[q][w];
            out[((size_t)b * NTQ + q0 + q) * NTK + t2] = ex[q] * __frcp_rn(s);
        }
    }
}

// ---------------------------------------------------------------------------
extern "C" void kernel_launch(void* const* d_in, const int* in_sizes, int n_in,
                              void* d_out, int out_size)
{
    const float* Q    = (const float*)d_in[0];
    const float* K    = (const float*)d_in[1];
    const int*   mask = (const int*)d_in[2];
    const float* W1   = (const float*)d_in[3];
    const float* W2   = (const float*)d_in[4];
    const float* w3   = (const float*)d_in[5];
    float*       out  = (float*)d_out;

    cudaFuncSetAttribute(proj_tc_kernel,
                         cudaFuncAttributeMaxDynamicSharedMemorySize, SMEM_DYN);

    dim3 gp(NA / BN, (NB * NTQ) / BM, 2);   // 8 x 8 x 2 = 128 CTAs
    proj_tc_kernel<<<gp, 256, SMEM_DYN>>>(Q, K, W1, W2);

    score_kernel<<<NB * NTQ / 4, 512>>>(mask, w3, out);   // 256 CTAs, one wave
}

// round 15
// speedup vs baseline: 2.1922x; 1.0007x over previous
#include <cuda_runtime.h>
#include <cuda_fp16.h>
#include <cstdint>
#include <cstddef>

// Problem constants
#define NB   4
#define NTQ  256
#define NTK  256
#define ND   1024
#define NA   512

// Scratch (allocation-free rule: __device__ globals).
__device__ __half2 g_qph[NB * NTQ * (NA / 2)];     // [b*TQ+q][a/2]
__device__ uint4   g_kp4[(NA / 8) * NB * NTK];     // [a/8][b*TK+t] : 4x half2

// ---------------------------------------------------------------------------
// Helpers
// ---------------------------------------------------------------------------
__device__ __forceinline__ uint32_t cvta_shared_u32(const void* p) {
    uint32_t a;
    asm("{ .reg .u64 t; cvta.to.shared.u64 t, %1; cvt.u32.u64 %0, t; }"
        : "=r"(a) : "l"(p));
    return a;
}

__device__ __forceinline__ void ldsm_x4(uint32_t* r, uint32_t addr) {
    asm volatile("ldmatrix.sync.aligned.m8n8.x4.shared.b16 {%0,%1,%2,%3}, [%4];"
                 : "=r"(r[0]), "=r"(r[1]), "=r"(r[2]), "=r"(r[3]) : "r"(addr));
}

__device__ __forceinline__ void mma_f16(float* c, const uint32_t* a, const uint32_t* b) {
    asm volatile(
        "mma.sync.aligned.m16n8k16.row.col.f32.f16.f16.f32 "
        "{%0,%1,%2,%3}, {%4,%5,%6,%7}, {%8,%9}, {%0,%1,%2,%3};"
        : "+f"(c[0]), "+f"(c[1]), "+f"(c[2]), "+f"(c[3])
        : "r"(a[0]), "r"(a[1]), "r"(a[2]), "r"(a[3]), "r"(b[0]), "r"(b[1]));
}

__device__ __forceinline__ __half2 tanh_h2(__half2 x) {
    uint32_t xi = *(uint32_t*)&x, r;
    asm("tanh.approx.f16x2 %0, %1;" : "=r"(r) : "r"(xi));
    return *(__half2*)&r;
}

__device__ __forceinline__ uint32_t h2bits(__half2 h) { return *(uint32_t*)&h; }

// ---------------------------------------------------------------------------
// Tensor-core projection GEMM, plain fp16 mma.sync (fp32 accumulate).
// z=0: Q*W1 -> g_qph (row-major, half2-packed over a).
// z=1: K*W2 -> g_kp4 ([a/8][bt] uint4-packed groups of 8 a's).
// ---------------------------------------------------------------------------
#define BM 128
#define BN 64
#define BK 64
#define RS 72                    // smem row stride in fp16 (144 B)
#define A_TILE_B  (BM * RS * 2)  // 18432
#define B_TILE_B  (BN * RS * 2)  //  9216
#define STAGE_B   (A_TILE_B + B_TILE_B)   // Ah, Bh = 27648
#define OFF_AH 0
#define OFF_BH A_TILE_B
#define SMEM_DYN (2 * STAGE_B)   // 55296

extern __shared__ char dynsmem[];

__global__ __launch_bounds__(256, 1) void proj_tc_kernel(
    const float* __restrict__ Qin, const float* __restrict__ Kin,
    const float* __restrict__ W1,  const float* __restrict__ W2)
{
    const int z  = blockIdx.z;
    const float* X = z ? Kin : Qin;
    const float* W = z ? W2  : W1;
    const int m0 = blockIdx.y * BM;
    const int n0 = blockIdx.x * BN;

    const int tid  = threadIdx.x;
    const int wid  = tid >> 5;
    const int lane = tid & 31;
    const int wm   = wid >> 1;        // 0..3
    const int wn   = wid & 1;         // 0..1

    const uint32_t sbase = cvta_shared_u32(dynsmem);

    const int a_row = (lane & 7) + ((lane >> 3) & 1) * 8;   // 0..15
    const int a_kof = (lane >> 4) * 8;                      // 0 / 8
    const int b_row = (lane & 7) + ((lane >> 4) & 1) * 8;
    const int b_kof = ((lane >> 3) & 1) * 8;

    float acc[2][4][4] = {};   // [mi][nf][4]

    float4 va[8], vb[4];

    auto load_regs = [&](int ch) {
        const int k0 = ch * BK;
        #pragma unroll
        for (int i = 0; i < 8; i++) {
            const int idx = tid + i * 256;
            const int row = idx >> 4;
            const int c4  = (idx & 15) * 4;
            va[i] = *(const float4*)(X + (size_t)(m0 + row) * ND + k0 + c4);
        }
        #pragma unroll
        for (int i = 0; i < 4; i++) {
            const int idx = tid + i * 256;
            const int row = idx >> 4;
            const int c4  = (idx & 15) * 4;
            vb[i] = *(const float4*)(W + (size_t)(n0 + row) * ND + k0 + c4);
        }
    };

    auto store_smem = [&](int s) {
        char* st = dynsmem + s * STAGE_B;
        #pragma unroll
        for (int i = 0; i < 8; i++) {
            const int idx = tid + i * 256;
            const int row = idx >> 4;
            const int c4  = idx & 15;
            const uint32_t off = (uint32_t)(row * (RS * 2) + c4 * 8);
            __half2 h01 = __floats2half2_rn(va[i].x, va[i].y);
            __half2 h23 = __floats2half2_rn(va[i].z, va[i].w);
            *(uint2*)(st + OFF_AH + off) = make_uint2(h2bits(h01), h2bits(h23));
        }
        #pragma unroll
        for (int i = 0; i < 4; i++) {
            const int idx = tid + i * 256;
            const int row = idx >> 4;
            const int c4  = idx & 15;
            const uint32_t off = (uint32_t)(row * (RS * 2) + c4 * 8);
            __half2 h01 = __floats2half2_rn(vb[i].x, vb[i].y);
            __half2 h23 = __floats2half2_rn(vb[i].z, vb[i].w);
            *(uint2*)(st + OFF_BH + off) = make_uint2(h2bits(h01), h2bits(h23));
        }
    };

    auto compute = [&](int s) {
        const uint32_t st = sbase + (uint32_t)(s * STAGE_B);
        #pragma unroll
        for (int ks = 0; ks < 4; ks++) {
            const uint32_t kb = (uint32_t)(ks * 16 * 2);
            uint32_t ah[2][4], bh[4][2];
            #pragma unroll
            for (int mi = 0; mi < 2; mi++) {
                const uint32_t ra = st + (uint32_t)((wm * 32 + mi * 16 + a_row) * (RS * 2))
                                   + kb + (uint32_t)(a_kof * 2);
                ldsm_x4(ah[mi], ra + OFF_AH);
            }
            #pragma unroll
            for (int bi = 0; bi < 2; bi++) {
                const uint32_t rb = st + (uint32_t)((wn * 32 + bi * 16 + b_row) * (RS * 2))
                                   + kb + (uint32_t)(b_kof * 2);
                uint32_t t0[4];
                ldsm_x4(t0, rb + OFF_BH);
                bh[bi*2+0][0] = t0[0]; bh[bi*2+0][1] = t0[1];
                bh[bi*2+1][0] = t0[2]; bh[bi*2+1][1] = t0[3];
            }
            #pragma unroll
            for (int mi = 0; mi < 2; mi++)
                #pragma unroll
                for (int nf = 0; nf < 4; nf++)
                    mma_f16(acc[mi][nf], ah[mi], bh[nf]);
        }
    };

    load_regs(0);
    store_smem(0);
    __syncthreads();

    for (int ch = 0; ch < 16; ch++) {
        const int s = ch & 1;
        if (ch < 15) load_regs(ch + 1);
        compute(s);
        if (ch < 15) store_smem(s ^ 1);
        __syncthreads();
    }

    // -------- Epilogue: stage 128x64 fp32 tile in smem (stride 65) --------
    float* ep = (float*)dynsmem;
    #pragma unroll
    for (int mi = 0; mi < 2; mi++)
        #pragma unroll
        for (int nf = 0; nf < 4; nf++)
            #pragma unroll
            for (int j = 0; j < 4; j++) {
                const int r = wm * 32 + mi * 16 + (lane >> 2) + (j >> 1) * 8;
                const int c = wn * 32 + nf * 8 + (lane & 3) * 2 + (j & 1);
                ep[r * 65 + c] = acc[mi][nf][j];
            }
    __syncthreads();

    if (z == 0) {
        #pragma unroll
        for (int i = 0; i < 16; i++) {
            const int idx = tid + i * 256;    // 0..4095
            const int row = idx >> 5;         // 0..127
            const int c2  = idx & 31;         // 0..31
            __half2 h = __floats2half2_rn(ep[row * 65 + 2 * c2],
                                          ep[row * 65 + 2 * c2 + 1]);
            g_qph[(size_t)(m0 + row) * (NA / 2) + (n0 >> 1) + c2] = h;
        }
    } else {
        #pragma unroll
        for (int i = 0; i < 4; i++) {
            const int idx = tid + i * 256;    // 0..1023
            const int m   = idx & 127;        // 0..127
            const int gg  = idx >> 7;         // 0..7
            const float* row = &ep[m * 65 + 8 * gg];
            __half2 h0 = __floats2half2_rn(row[0], row[1]);
            __half2 h1 = __floats2half2_rn(row[2], row[3]);
            __half2 h2 = __floats2half2_rn(row[4], row[5]);
            __half2 h3 = __floats2half2_rn(row[6], row[7]);
            uint4 v;
            v.x = h2bits(h0); v.y = h2bits(h1);
            v.z = h2bits(h2); v.w = h2bits(h3);
            g_kp4[(size_t)((n0 >> 3) + gg) * (NB * NTK) + m0 + m] = v;
        }
    }
}

// ---------------------------------------------------------------------------
// Fused score + masked softmax, v10: item = (b, 1 q-row), 1024 CTAs x 128
// threads, 8 CTAs/SM -> all CTAs resident, no waves, self-balancing under
// latency-bound execution. Mainloop body identical to v9.
// ---------------------------------------------------------------------------
#define KSTRIDE (NB * NTK)      // uint4 elements between a-groups

__global__ __launch_bounds__(128, 8) void score_kernel(
    const int* __restrict__ mask, const float* __restrict__ w3,
    float* __restrict__ out)
{
    __shared__ __align__(16) uint4 qp4s[NA / 8];   // 64 (this q row)
    __shared__ __align__(16) uint4 w34[NA / 8];
    __shared__ float acc_s[NTK];
    __shared__ short idx_s[NTK];
    __shared__ unsigned ball_s[8];
    __shared__ int   wcnt[8], wbase[9];
    __shared__ float redm[4], reds[4];

    const int tid  = threadIdx.x;           // 0..127
    const int wrp  = tid >> 5;              // 0..3
    const int lane = tid & 31;
    const int item = blockIdx.x;            // 0..1023 == b*NTQ + q
    const int b    = item >> 8;

    // stage qp row + w3
    if (tid < 64) qp4s[tid] = ((const uint4*)g_qph)[(size_t)item * 64 + tid];
    ((__half2*)w34)[tid]       = __floats2half2_rn(w3[2 * tid],       w3[2 * tid + 1]);
    ((__half2*)w34)[tid + 128] = __floats2half2_rn(w3[2 * tid + 256], w3[2 * tid + 257]);

    // ---- mask ballot-compaction (2 t's per thread: tid, tid+128)
    const int mv0 = mask[(size_t)item * NTK + tid];
    const int mv1 = mask[(size_t)item * NTK + 128 + tid];
    const unsigned bal0 = __ballot_sync(0xffffffffu, mv0 != 0);  // seg wrp
    const unsigned bal1 = __ballot_sync(0xffffffffu, mv1 != 0);  // seg wrp+4
    if (lane == 0) {
        wcnt[wrp] = __popc(bal0);   ball_s[wrp] = bal0;
        wcnt[wrp + 4] = __popc(bal1); ball_s[wrp + 4] = bal1;
    }
    const int pos0 = __popc(bal0 & ((1u << lane) - 1));
    const int pos1 = __popc(bal1 & ((1u << lane) - 1));

    acc_s[tid]       = 0.f;
    acc_s[tid + 128] = 0.f;
    __syncthreads();

    if (tid == 0) {
        int s = 0;
        #pragma unroll
        for (int w = 0; w < 8; w++) { wbase[w] = s; s += wcnt[w]; }
        wbase[8] = s;
    }
    __syncthreads();

    if (mv0) idx_s[wbase[wrp] + pos0]     = (short)tid;
    if (mv1) idx_s[wbase[wrp + 4] + pos1] = (short)(128 + tid);
    __syncthreads();

    const int total = wbase[8];
    const int units = total * 4;

    for (int u = tid; u < units; u += 128) {
        // chunk-major decode
        int c = 0, pr = u;
        if (pr >= total) { c++; pr -= total; }
        if (pr >= total) { c++; pr -= total; }
        if (pr >= total) { c++; pr -= total; }
        const int t = idx_s[pr];
        const uint4* gk = g_kp4 + (size_t)(c * 16) * KSTRIDE + (size_t)b * NTK + t;

        float acc = 0.f;
        uint4 kc0 = __ldg(gk);
        uint4 kc1 = __ldg(gk + KSTRIDE);

        #pragma unroll
        for (int jj = 0; jj < 8; jj++) {
            uint4 kn0, kn1;
            if (jj < 7) {
                kn0 = __ldg(gk + (size_t)(2 * jj + 2) * KSTRIDE);
                kn1 = __ldg(gk + (size_t)(2 * jj + 3) * KSTRIDE);
            }
            const int base = c * 16 + 2 * jj;
            uint4 uw0 = w34[base], uw1 = w34[base + 1];
            uint4 uq0 = qp4s[base], uq1 = qp4s[base + 1];
            const uint32_t* w0 = (const uint32_t*)&uw0;
            const uint32_t* w1 = (const uint32_t*)&uw1;
            const uint32_t* qv0 = (const uint32_t*)&uq0;
            const uint32_t* qv1 = (const uint32_t*)&uq1;
            const uint32_t* k0 = (const uint32_t*)&kc0;
            const uint32_t* k1 = (const uint32_t*)&kc1;

            __half2 aA = __floats2half2_rn(0.f, 0.f);
            __half2 aB = aA, aC = aA, aD = aA;
            {
                __half2 t0 = tanh_h2(__hadd2(*(__half2*)&qv0[0], *(__half2*)&k0[0]));
                __half2 t1 = tanh_h2(__hadd2(*(__half2*)&qv0[1], *(__half2*)&k0[1]));
                __half2 t2_ = tanh_h2(__hadd2(*(__half2*)&qv0[2], *(__half2*)&k0[2]));
                __half2 t3 = tanh_h2(__hadd2(*(__half2*)&qv0[3], *(__half2*)&k0[3]));
                aA = __hfma2(*(__half2*)&w0[0], t0, aA);
                aB = __hfma2(*(__half2*)&w0[1], t1, aB);
                aC = __hfma2(*(__half2*)&w0[2], t2_, aC);
                aD = __hfma2(*(__half2*)&w0[3], t3, aD);
            }
            {
                __half2 t0 = tanh_h2(__hadd2(*(__half2*)&qv1[0], *(__half2*)&k1[0]));
                __half2 t1 = tanh_h2(__hadd2(*(__half2*)&qv1[1], *(__half2*)&k1[1]));
                __half2 t2_ = tanh_h2(__hadd2(*(__half2*)&qv1[2], *(__half2*)&k1[2]));
                __half2 t3 = tanh_h2(__hadd2(*(__half2*)&qv1[3], *(__half2*)&k1[3]));
                aA = __hfma2(*(__half2*)&w1[0], t0, aA);
                aB = __hfma2(*(__half2*)&w1[1], t1, aB);
                aC = __hfma2(*(__half2*)&w1[2], t2_, aC);
                aD = __hfma2(*(__half2*)&w1[3], t3, aD);
            }
            __half2 hs = __hadd2(__hadd2(aA, aB), __hadd2(aC, aD));
            acc += __low2float(hs) + __high2float(hs);

            if (jj < 7) { kc0 = kn0; kc1 = kn1; }
        }

        atomicAdd(&acc_s[t], acc);
    }
    __syncthreads();

    // ---- softmax over 256 t (2 per thread; mask applied from ballots)
    const unsigned bit0 = (ball_s[wrp]     >> lane) & 1u;
    const unsigned bit1 = (ball_s[wrp + 4] >> lane) & 1u;
    const float sc0 = bit0 ? acc_s[tid]       : -1e10f;
    const float sc1 = bit1 ? acc_s[tid + 128] : -1e10f;

    {
        float v = fmaxf(sc0, sc1);
        #pragma unroll
        for (int o = 16; o; o >>= 1) v = fmaxf(v, __shfl_xor_sync(0xffffffffu, v, o));
        if (lane == 0) redm[wrp] = v;
    }
    __syncthreads();

    const float m = fmaxf(fmaxf(redm[0], redm[1]), fmaxf(redm[2], redm[3]));
    const float ex0 = exp2f((sc0 - m) * 1.4426950408889634f);
    const float ex1 = exp2f((sc1 - m) * 1.4426950408889634f);
    {
        float v = ex0 + ex1;
        #pragma unroll
        for (int o = 16; o; o >>= 1) v += __shfl_xor_sync(0xffffffffu, v, o);
        if (lane == 0) reds[wrp] = v;
    }
    __syncthreads();

    const float s = (reds[0] + reds[1]) + (reds[2] + reds[3]);
    const float r = __frcp_rn(s);
    out[(size_t)item * NTK + tid]       = ex0 * r;
    out[(size_t)item * NTK + 128 + tid] = ex1 * r;
}

// ---------------------------------------------------------------------------
extern "C" void kernel_launch(void* const* d_in, const int* in_sizes, int n_in,
                              void* d_out, int out_size)
{
    const float* Q    = (const float*)d_in[0];
    const float* K    = (const float*)d_in[1];
    const int*   mask = (const int*)d_in[2];
    const float* W1   = (const float*)d_in[3];
    const float* W2   = (const float*)d_in[4];
    const float* w3   = (const float*)d_in[5];
    float*       out  = (float*)d_out;

    cudaFuncSetAttribute(proj_tc_kernel,
                         cudaFuncAttributeMaxDynamicSharedMemorySize, SMEM_DYN);

    dim3 gp(NA / BN, (NB * NTQ) / BM, 2);   // 8 x 8 x 2 = 128 CTAs
    proj_tc_kernel<<<gp, 256, SMEM_DYN>>>(Q, K, W1, W2);

    score_kernel<<<NB * NTQ, 128>>>(mask, w3, out);   // 1024 CTAs, all resident
}

// round 16
// speedup vs baseline: 2.2761x; 1.0383x over previous
#include <cuda_runtime.h>
#include <cuda_fp16.h>
#include <cstdint>
#include <cstddef>

// Problem constants
#define NB   4
#define NTQ  256
#define NTK  256
#define ND   1024
#define NA   512

// Scratch (allocation-free rule: __device__ globals).
__device__ __half2 g_qph[NB * NTQ * (NA / 2)];     // [b*TQ+q][a/2]
__device__ uint4   g_kp4[(NA / 8) * NB * NTK];     // [a/8][b*TK+t] : 4x half2

// ---------------------------------------------------------------------------
// Helpers
// ---------------------------------------------------------------------------
__device__ __forceinline__ uint32_t cvta_shared_u32(const void* p) {
    uint32_t a;
    asm("{ .reg .u64 t; cvta.to.shared.u64 t, %1; cvt.u32.u64 %0, t; }"
        : "=r"(a) : "l"(p));
    return a;
}

__device__ __forceinline__ void ldsm_x4(uint32_t* r, uint32_t addr) {
    asm volatile("ldmatrix.sync.aligned.m8n8.x4.shared.b16 {%0,%1,%2,%3}, [%4];"
                 : "=r"(r[0]), "=r"(r[1]), "=r"(r[2]), "=r"(r[3]) : "r"(addr));
}

__device__ __forceinline__ void mma_f16(float* c, const uint32_t* a, const uint32_t* b) {
    asm volatile(
        "mma.sync.aligned.m16n8k16.row.col.f32.f16.f16.f32 "
        "{%0,%1,%2,%3}, {%4,%5,%6,%7}, {%8,%9}, {%0,%1,%2,%3};"
        : "+f"(c[0]), "+f"(c[1]), "+f"(c[2]), "+f"(c[3])
        : "r"(a[0]), "r"(a[1]), "r"(a[2]), "r"(a[3]), "r"(b[0]), "r"(b[1]));
}

__device__ __forceinline__ __half2 tanh_h2(__half2 x) {
    uint32_t xi = *(uint32_t*)&x, r;
    asm("tanh.approx.f16x2 %0, %1;" : "=r"(r) : "r"(xi));
    return *(__half2*)&r;
}

__device__ __forceinline__ uint32_t h2bits(__half2 h) { return *(uint32_t*)&h; }

// ---------------------------------------------------------------------------
// Tensor-core projection GEMM, plain fp16 mma.sync (fp32 accumulate).
// z=0: Q*W1 -> g_qph (row-major, half2-packed over a).
// z=1: K*W2 -> g_kp4 ([a/8][bt] uint4-packed groups of 8 a's).
// ---------------------------------------------------------------------------
#define BM 128
#define BN 64
#define BK 64
#define RS 72                    // smem row stride in fp16 (144 B)
#define A_TILE_B  (BM * RS * 2)  // 18432
#define B_TILE_B  (BN * RS * 2)  //  9216
#define STAGE_B   (A_TILE_B + B_TILE_B)   // Ah, Bh = 27648
#define OFF_AH 0
#define OFF_BH A_TILE_B
#define SMEM_DYN (2 * STAGE_B)   // 55296

extern __shared__ char dynsmem[];

__global__ __launch_bounds__(256, 1) void proj_tc_kernel(
    const float* __restrict__ Qin, const float* __restrict__ Kin,
    const float* __restrict__ W1,  const float* __restrict__ W2)
{
    const int z  = blockIdx.z;
    const float* X = z ? Kin : Qin;
    const float* W = z ? W2  : W1;
    const int m0 = blockIdx.y * BM;
    const int n0 = blockIdx.x * BN;

    const int tid  = threadIdx.x;
    const int wid  = tid >> 5;
    const int lane = tid & 31;
    const int wm   = wid >> 1;        // 0..3
    const int wn   = wid & 1;         // 0..1

    const uint32_t sbase = cvta_shared_u32(dynsmem);

    const int a_row = (lane & 7) + ((lane >> 3) & 1) * 8;   // 0..15
    const int a_kof = (lane >> 4) * 8;                      // 0 / 8
    const int b_row = (lane & 7) + ((lane >> 4) & 1) * 8;
    const int b_kof = ((lane >> 3) & 1) * 8;

    float acc[2][4][4] = {};   // [mi][nf][4]

    float4 va[8], vb[4];

    auto load_regs = [&](int ch) {
        const int k0 = ch * BK;
        #pragma unroll
        for (int i = 0; i < 8; i++) {
            const int idx = tid + i * 256;
            const int row = idx >> 4;
            const int c4  = (idx & 15) * 4;
            va[i] = *(const float4*)(X + (size_t)(m0 + row) * ND + k0 + c4);
        }
        #pragma unroll
        for (int i = 0; i < 4; i++) {
            const int idx = tid + i * 256;
            const int row = idx >> 4;
            const int c4  = (idx & 15) * 4;
            vb[i] = *(const float4*)(W + (size_t)(n0 + row) * ND + k0 + c4);
        }
    };

    auto store_smem = [&](int s) {
        char* st = dynsmem + s * STAGE_B;
        #pragma unroll
        for (int i = 0; i < 8; i++) {
            const int idx = tid + i * 256;
            const int row = idx >> 4;
            const int c4  = idx & 15;
            const uint32_t off = (uint32_t)(row * (RS * 2) + c4 * 8);
            __half2 h01 = __floats2half2_rn(va[i].x, va[i].y);
            __half2 h23 = __floats2half2_rn(va[i].z, va[i].w);
            *(uint2*)(st + OFF_AH + off) = make_uint2(h2bits(h01), h2bits(h23));
        }
        #pragma unroll
        for (int i = 0; i < 4; i++) {
            const int idx = tid + i * 256;
            const int row = idx >> 4;
            const int c4  = idx & 15;
            const uint32_t off = (uint32_t)(row * (RS * 2) + c4 * 8);
            __half2 h01 = __floats2half2_rn(vb[i].x, vb[i].y);
            __half2 h23 = __floats2half2_rn(vb[i].z, vb[i].w);
            *(uint2*)(st + OFF_BH + off) = make_uint2(h2bits(h01), h2bits(h23));
        }
    };

    auto compute = [&](int s) {
        const uint32_t st = sbase + (uint32_t)(s * STAGE_B);
        #pragma unroll
        for (int ks = 0; ks < 4; ks++) {
            const uint32_t kb = (uint32_t)(ks * 16 * 2);
            uint32_t ah[2][4], bh[4][2];
            #pragma unroll
            for (int mi = 0; mi < 2; mi++) {
                const uint32_t ra = st + (uint32_t)((wm * 32 + mi * 16 + a_row) * (RS * 2))
                                   + kb + (uint32_t)(a_kof * 2);
                ldsm_x4(ah[mi], ra + OFF_AH);
            }
            #pragma unroll
            for (int bi = 0; bi < 2; bi++) {
                const uint32_t rb = st + (uint32_t)((wn * 32 + bi * 16 + b_row) * (RS * 2))
                                   + kb + (uint32_t)(b_kof * 2);
                uint32_t t0[4];
                ldsm_x4(t0, rb + OFF_BH);
                bh[bi*2+0][0] = t0[0]; bh[bi*2+0][1] = t0[1];
                bh[bi*2+1][0] = t0[2]; bh[bi*2+1][1] = t0[3];
            }
            #pragma unroll
            for (int mi = 0; mi < 2; mi++)
                #pragma unroll
                for (int nf = 0; nf < 4; nf++)
                    mma_f16(acc[mi][nf], ah[mi], bh[nf]);
        }
    };

    load_regs(0);
    store_smem(0);
    __syncthreads();

    for (int ch = 0; ch < 16; ch++) {
        const int s = ch & 1;
        if (ch < 15) load_regs(ch + 1);
        compute(s);
        if (ch < 15) store_smem(s ^ 1);
        __syncthreads();
    }

    // -------- Epilogue: stage 128x64 fp32 tile in smem (stride 65) --------
    float* ep = (float*)dynsmem;
    #pragma unroll
    for (int mi = 0; mi < 2; mi++)
        #pragma unroll
        for (int nf = 0; nf < 4; nf++)
            #pragma unroll
            for (int j = 0; j < 4; j++) {
                const int r = wm * 32 + mi * 16 + (lane >> 2) + (j >> 1) * 8;
                const int c = wn * 32 + nf * 8 + (lane & 3) * 2 + (j & 1);
                ep[r * 65 + c] = acc[mi][nf][j];
            }
    __syncthreads();

    if (z == 0) {
        #pragma unroll
        for (int i = 0; i < 16; i++) {
            const int idx = tid + i * 256;    // 0..4095
            const int row = idx >> 5;         // 0..127
            const int c2  = idx & 31;         // 0..31
            __half2 h = __floats2half2_rn(ep[row * 65 + 2 * c2],
                                          ep[row * 65 + 2 * c2 + 1]);
            g_qph[(size_t)(m0 + row) * (NA / 2) + (n0 >> 1) + c2] = h;
        }
    } else {
        #pragma unroll
        for (int i = 0; i < 4; i++) {
            const int idx = tid + i * 256;    // 0..1023
            const int m   = idx & 127;        // 0..127
            const int gg  = idx >> 7;         // 0..7
            const float* row = &ep[m * 65 + 8 * gg];
            __half2 h0 = __floats2half2_rn(row[0], row[1]);
            __half2 h1 = __floats2half2_rn(row[2], row[3]);
            __half2 h2 = __floats2half2_rn(row[4], row[5]);
            __half2 h3 = __floats2half2_rn(row[6], row[7]);
            uint4 v;
            v.x = h2bits(h0); v.y = h2bits(h1);
            v.z = h2bits(h2); v.w = h2bits(h3);
            g_kp4[(size_t)((n0 >> 3) + gg) * (NB * NTK) + m0 + m] = v;
        }
    }
}

// ---------------------------------------------------------------------------
// Fused score + masked softmax, v11: v10 + depth-2 circular prefetch buffer
// (same 16 k-registers, lookahead doubled to 2 stages; loads issued before
// the tanh chain of the current stage).
// ---------------------------------------------------------------------------
#define KSTRIDE (NB * NTK)      // uint4 elements between a-groups

__global__ __launch_bounds__(128, 8) void score_kernel(
    const int* __restrict__ mask, const float* __restrict__ w3,
    float* __restrict__ out)
{
    __shared__ __align__(16) uint4 qp4s[NA / 8];   // 64 (this q row)
    __shared__ __align__(16) uint4 w34[NA / 8];
    __shared__ float acc_s[NTK];
    __shared__ short idx_s[NTK];
    __shared__ unsigned ball_s[8];
    __shared__ int   wcnt[8], wbase[9];
    __shared__ float redm[4], reds[4];

    const int tid  = threadIdx.x;           // 0..127
    const int wrp  = tid >> 5;              // 0..3
    const int lane = tid & 31;
    const int item = blockIdx.x;            // 0..1023 == b*NTQ + q
    const int b    = item >> 8;

    // stage qp row + w3
    if (tid < 64) qp4s[tid] = ((const uint4*)g_qph)[(size_t)item * 64 + tid];
    ((__half2*)w34)[tid]       = __floats2half2_rn(w3[2 * tid],       w3[2 * tid + 1]);
    ((__half2*)w34)[tid + 128] = __floats2half2_rn(w3[2 * tid + 256], w3[2 * tid + 257]);

    // ---- mask ballot-compaction (2 t's per thread: tid, tid+128)
    const int mv0 = mask[(size_t)item * NTK + tid];
    const int mv1 = mask[(size_t)item * NTK + 128 + tid];
    const unsigned bal0 = __ballot_sync(0xffffffffu, mv0 != 0);  // seg wrp
    const unsigned bal1 = __ballot_sync(0xffffffffu, mv1 != 0);  // seg wrp+4
    if (lane == 0) {
        wcnt[wrp] = __popc(bal0);   ball_s[wrp] = bal0;
        wcnt[wrp + 4] = __popc(bal1); ball_s[wrp + 4] = bal1;
    }
    const int pos0 = __popc(bal0 & ((1u << lane) - 1));
    const int pos1 = __popc(bal1 & ((1u << lane) - 1));

    acc_s[tid]       = 0.f;
    acc_s[tid + 128] = 0.f;
    __syncthreads();

    if (tid == 0) {
        int s = 0;
        #pragma unroll
        for (int w = 0; w < 8; w++) { wbase[w] = s; s += wcnt[w]; }
        wbase[8] = s;
    }
    __syncthreads();

    if (mv0) idx_s[wbase[wrp] + pos0]     = (short)tid;
    if (mv1) idx_s[wbase[wrp + 4] + pos1] = (short)(128 + tid);
    __syncthreads();

    const int total = wbase[8];
    const int units = total * 4;

    for (int u = tid; u < units; u += 128) {
        // chunk-major decode
        int c = 0, pr = u;
        if (pr >= total) { c++; pr -= total; }
        if (pr >= total) { c++; pr -= total; }
        if (pr >= total) { c++; pr -= total; }
        const int t = idx_s[pr];
        const uint4* gk = g_kp4 + (size_t)(c * 16) * KSTRIDE + (size_t)b * NTK + t;

        float acc = 0.f;

        // depth-2 circular prefetch: buf holds stages j and j+1
        uint4 buf[2][2];
        buf[0][0] = __ldg(gk);
        buf[0][1] = __ldg(gk + KSTRIDE);
        buf[1][0] = __ldg(gk + 2 * KSTRIDE);
        buf[1][1] = __ldg(gk + 3 * KSTRIDE);

        #pragma unroll
        for (int jj = 0; jj < 8; jj++) {
            const uint4 kc0 = buf[jj & 1][0];
            const uint4 kc1 = buf[jj & 1][1];
            if (jj < 6) {   // load stage jj+2 into the freed slot, before compute
                buf[jj & 1][0] = __ldg(gk + (size_t)(2 * jj + 4) * KSTRIDE);
                buf[jj & 1][1] = __ldg(gk + (size_t)(2 * jj + 5) * KSTRIDE);
            }
            const int base = c * 16 + 2 * jj;
            uint4 uw0 = w34[base], uw1 = w34[base + 1];
            uint4 uq0 = qp4s[base], uq1 = qp4s[base + 1];
            const uint32_t* w0 = (const uint32_t*)&uw0;
            const uint32_t* w1 = (const uint32_t*)&uw1;
            const uint32_t* qv0 = (const uint32_t*)&uq0;
            const uint32_t* qv1 = (const uint32_t*)&uq1;
            const uint32_t* k0 = (const uint32_t*)&kc0;
            const uint32_t* k1 = (const uint32_t*)&kc1;

            __half2 aA = __floats2half2_rn(0.f, 0.f);
            __half2 aB = aA, aC = aA, aD = aA;
            {
                __half2 t0 = tanh_h2(__hadd2(*(__half2*)&qv0[0], *(__half2*)&k0[0]));
                __half2 t1 = tanh_h2(__hadd2(*(__half2*)&qv0[1], *(__half2*)&k0[1]));
                __half2 t2_ = tanh_h2(__hadd2(*(__half2*)&qv0[2], *(__half2*)&k0[2]));
                __half2 t3 = tanh_h2(__hadd2(*(__half2*)&qv0[3], *(__half2*)&k0[3]));
                aA = __hfma2(*(__half2*)&w0[0], t0, aA);
                aB = __hfma2(*(__half2*)&w0[1], t1, aB);
                aC = __hfma2(*(__half2*)&w0[2], t2_, aC);
                aD = __hfma2(*(__half2*)&w0[3], t3, aD);
            }
            {
                __half2 t0 = tanh_h2(__hadd2(*(__half2*)&qv1[0], *(__half2*)&k1[0]));
                __half2 t1 = tanh_h2(__hadd2(*(__half2*)&qv1[1], *(__half2*)&k1[1]));
                __half2 t2_ = tanh_h2(__hadd2(*(__half2*)&qv1[2], *(__half2*)&k1[2]));
                __half2 t3 = tanh_h2(__hadd2(*(__half2*)&qv1[3], *(__half2*)&k1[3]));
                aA = __hfma2(*(__half2*)&w1[0], t0, aA);
                aB = __hfma2(*(__half2*)&w1[1], t1, aB);
                aC = __hfma2(*(__half2*)&w1[2], t2_, aC);
                aD = __hfma2(*(__half2*)&w1[3], t3, aD);
            }
            __half2 hs = __hadd2(__hadd2(aA, aB), __hadd2(aC, aD));
            acc += __low2float(hs) + __high2float(hs);
        }

        atomicAdd(&acc_s[t], acc);
    }
    __syncthreads();

    // ---- softmax over 256 t (2 per thread; mask applied from ballots)
    const unsigned bit0 = (ball_s[wrp]     >> lane) & 1u;
    const unsigned bit1 = (ball_s[wrp + 4] >> lane) & 1u;
    const float sc0 = bit0 ? acc_s[tid]       : -1e10f;
    const float sc1 = bit1 ? acc_s[tid + 128] : -1e10f;

    {
        float v = fmaxf(sc0, sc1);
        #pragma unroll
        for (int o = 16; o; o >>= 1) v = fmaxf(v, __shfl_xor_sync(0xffffffffu, v, o));
        if (lane == 0) redm[wrp] = v;
    }
    __syncthreads();

    const float m = fmaxf(fmaxf(redm[0], redm[1]), fmaxf(redm[2], redm[3]));
    const float ex0 = exp2f((sc0 - m) * 1.4426950408889634f);
    const float ex1 = exp2f((sc1 - m) * 1.4426950408889634f);
    {
        float v = ex0 + ex1;
        #pragma unroll
        for (int o = 16; o; o >>= 1) v += __shfl_xor_sync(0xffffffffu, v, o);
        if (lane == 0) reds[wrp] = v;
    }
    __syncthreads();

    const float s = (reds[0] + reds[1]) + (reds[2] + reds[3]);
    const float r = __frcp_rn(s);
    out[(size_t)item * NTK + tid]       = ex0 * r;
    out[(size_t)item * NTK + 128 + tid] = ex1 * r;
}

// ---------------------------------------------------------------------------
extern "C" void kernel_launch(void* const* d_in, const int* in_sizes, int n_in,
                              void* d_out, int out_size)
{
    const float* Q    = (const float*)d_in[0];
    const float* K    = (const float*)d_in[1];
    const int*   mask = (const int*)d_in[2];
    const float* W1   = (const float*)d_in[3];
    const float* W2   = (const float*)d_in[4];
    const float* w3   = (const float*)d_in[5];
    float*       out  = (float*)d_out;

    cudaFuncSetAttribute(proj_tc_kernel,
                         cudaFuncAttributeMaxDynamicSharedMemorySize, SMEM_DYN);

    dim3 gp(NA / BN, (NB * NTQ) / BM, 2);   // 8 x 8 x 2 = 128 CTAs
    proj_tc_kernel<<<gp, 256, SMEM_DYN>>>(Q, K, W1, W2);

    score_kernel<<<NB * NTQ, 128>>>(mask, w3, out);   // 1024 CTAs, all resident
}